// round 6
// baseline (speedup 1.0000x reference)
#include <cuda_runtime.h>
#include <cuda_bf16.h>

#define N_S    32
#define C_CH   64
#define HWsz   12544
#define HW4    3136            // HW / 4 (float4)
#define NB     13              // k1 blocks per sample (13*256 >= 3136)
#define HIDDEN 8
#define T_INV  (1.0f/10.0f)
#define GAMMA  (12544.0f/3.0f)

// Scratch (device globals — allocation is forbidden). Zero-init at load.
__device__ float4   g_s4[N_S * HW4];          // raw s (+bias)
__device__ float    g_cpart[N_S * NB * C_CH]; // per-block channel partials
__device__ float    g_epart[N_S * NB];        // per-block exp partials
__device__ float    g_coefA[N_S * 128];       // [n][k*64+c]
__device__ float    g_coefB[N_S * 128];
__device__ float    g_inv[N_S];               // GAMMA / sumexp
__device__ unsigned g_ticket[N_S];            // reset by last block each launch

// ============ K1: read x once -> s, partials; last block -> coefs ============
// grid (13, 32), block 256. Warp w owns channels [8w, 8w+8), 256 pos4/block.
__global__ void __launch_bounds__(256) k1_reduce(
    const float* __restrict__ x,
    const float* __restrict__ conv_w, const float* __restrict__ conv_b,
    const float* __restrict__ w1, const float* __restrict__ b1,
    const float* __restrict__ w2, const float* __restrict__ b2)
{
    const int n    = blockIdx.y;
    const int bx   = blockIdx.x;
    const int base = bx * 256;
    const int tid  = threadIdx.x;
    const int warp = tid >> 5, lane = tid & 31;
    const int c0   = warp * 8;

    __shared__ float4 ssh[8][256];   // per-warp partial s over its 8 channels
    __shared__ float  wsh[C_CH];
    __shared__ float  epart8[8];
    __shared__ unsigned oldt;

    if (tid < C_CH) wsh[tid] = conv_w[tid];
    __syncthreads();

    float pool[8];
    #pragma unroll
    for (int i = 0; i < 8; i++) pool[i] = 0.f;

    const float4* xb = reinterpret_cast<const float4*>(x)
                     + ((size_t)n * C_CH + c0) * HW4 + base + lane;

    #pragma unroll
    for (int it = 0; it < 8; it++) {
        const int pos = base + it * 32 + lane;
        const bool ok = pos < HW4;
        float4 s4 = make_float4(0.f, 0.f, 0.f, 0.f);
        #pragma unroll
        for (int c8 = 0; c8 < 8; c8++) {
            float4 v = ok ? xb[(size_t)c8 * HW4 + it * 32]
                          : make_float4(0.f, 0.f, 0.f, 0.f);
            float w = wsh[c0 + c8];
            pool[c8] += (v.x + v.y) + (v.z + v.w);
            s4.x = fmaf(v.x, w, s4.x); s4.y = fmaf(v.y, w, s4.y);
            s4.z = fmaf(v.z, w, s4.z); s4.w = fmaf(v.w, w, s4.w);
        }
        ssh[warp][it * 32 + lane] = s4;
    }

    #pragma unroll
    for (int c8 = 0; c8 < 8; c8++) {
        float p = pool[c8];
        p += __shfl_down_sync(0xffffffff, p, 16);
        p += __shfl_down_sync(0xffffffff, p, 8);
        p += __shfl_down_sync(0xffffffff, p, 4);
        p += __shfl_down_sync(0xffffffff, p, 2);
        p += __shfl_down_sync(0xffffffff, p, 1);
        pool[c8] = p;
    }
    if (lane == 0) {
        float* dst = &g_cpart[((size_t)n * NB + bx) * C_CH + c0];
        #pragma unroll
        for (int c8 = 0; c8 < 8; c8++) dst[c8] = pool[c8];
    }
    __syncthreads();

    // finalize s per position, write raw s, accumulate exp partial
    const int pos = base + tid;
    float e = 0.f;
    if (pos < HW4) {
        float4 s = ssh[0][tid];
        #pragma unroll
        for (int w = 1; w < 8; w++) {
            float4 t = ssh[w][tid];
            s.x += t.x; s.y += t.y; s.z += t.z; s.w += t.w;
        }
        const float bb = __ldg(conv_b);
        s.x += bb; s.y += bb; s.z += bb; s.w += bb;
        g_s4[n * HW4 + pos] = s;
        e = __expf(s.x * T_INV) + __expf(s.y * T_INV)
          + __expf(s.z * T_INV) + __expf(s.w * T_INV);
    }
    e += __shfl_down_sync(0xffffffff, e, 16);
    e += __shfl_down_sync(0xffffffff, e, 8);
    e += __shfl_down_sync(0xffffffff, e, 4);
    e += __shfl_down_sync(0xffffffff, e, 2);
    e += __shfl_down_sync(0xffffffff, e, 1);
    if (lane == 0) epart8[warp] = e;
    __syncthreads();
    if (tid == 0) {
        float acc = 0.f;
        #pragma unroll
        for (int w = 0; w < 8; w++) acc += epart8[w];
        g_epart[n * NB + bx] = acc;
    }

    // publish + ticket (threadfence reduction pattern)
    __threadfence();
    __syncthreads();
    if (tid == 0) oldt = atomicAdd(&g_ticket[n], 1);
    __syncthreads();
    if (oldt != NB - 1) return;

    // ---- last block of sample n: reduce partials, compute coefs ----
    __threadfence();                  // acquire other blocks' writes
    if (tid == 0) g_ticket[n] = 0;    // reset for next graph replay

    __shared__ float red[4][C_CH];
    __shared__ float ps[C_CH];
    __shared__ float hs[HIDDEN];
    {
        const int c = tid & 63, q = tid >> 6;   // 4-way split over units
        float a = 0.f;
        for (int j = q; j < NB; j += 4)
            a += __ldcg(&g_cpart[((size_t)n * NB + j) * C_CH + c]);
        red[q][c] = a;
    }
    if (warp == 0) {
        float se = 0.f;
        for (int j = lane; j < NB; j += 32) se += __ldcg(&g_epart[n * NB + j]);
        se += __shfl_down_sync(0xffffffff, se, 16);
        se += __shfl_down_sync(0xffffffff, se, 8);
        se += __shfl_down_sync(0xffffffff, se, 4);
        se += __shfl_down_sync(0xffffffff, se, 2);
        se += __shfl_down_sync(0xffffffff, se, 1);
        if (lane == 0) g_inv[n] = GAMMA / se;
    }
    __syncthreads();
    if (tid < C_CH)
        ps[tid] = (red[0][tid] + red[1][tid] + red[2][tid] + red[3][tid])
                * (1.0f / (float)HWsz);
    __syncthreads();
    if (tid < HIDDEN) {
        float a = __ldg(&b1[tid]);
        #pragma unroll
        for (int c = 0; c < C_CH; c++)
            a = fmaf(ps[c], __ldg(&w1[c * HIDDEN + tid]), a);
        hs[tid] = fmaxf(a, 0.0f);
    }
    __syncthreads();
    {
        float o = __ldg(&b2[tid]);
        #pragma unroll
        for (int j = 0; j < HIDDEN; j++)
            o = fmaf(hs[j], __ldg(&w2[j * 256 + tid]), o);
        float val = 2.0f / (1.0f + __expf(-o)) - 1.0f;   // 2*sigmoid-1
        const int sel = tid & 1;
        const int c   = (tid >> 1) & 63;
        const int k   = tid >> 7;
        const float init = (k == 0) ? 1.0f : 0.0f;
        if (sel == 0) g_coefA[n * 128 + k * 64 + c] = init + val;
        else          g_coefB[n * 128 + k * 64 + c] = init + 0.5f * val;
    }
}

// ================= K4: spatial + output pass (x re-read from L2) =============
// grid (49, 32), block 256: sample n, 64 pos4, all 64 channels.
// Loads batched 8-deep (MLP); stores write-through (no L2 allocate).
__global__ void __launch_bounds__(256) k4_out(
    const float* __restrict__ x, float* __restrict__ out)
{
    const int n   = blockIdx.y;
    const int p0  = blockIdx.x * 64;
    const int tid = threadIdx.x;

    __shared__ float a0s[C_CH], a1s[C_CH], b0s[C_CH], b1s[C_CH];
    __shared__ float4 sp4s[64];

    if (tid < 64) {
        a0s[tid] = g_coefA[n * 128 + tid];
        a1s[tid] = g_coefA[n * 128 + 64 + tid];
        b0s[tid] = g_coefB[n * 128 + tid];
        b1s[tid] = g_coefB[n * 128 + 64 + tid];
    } else if (tid < 128) {
        const int t = tid - 64;
        const float inv = g_inv[n];
        float4 s = g_s4[n * HW4 + p0 + t];
        float4 sp;
        sp.x = fminf(__expf(s.x * T_INV) * inv, 1.0f);
        sp.y = fminf(__expf(s.y * T_INV) * inv, 1.0f);
        sp.z = fminf(__expf(s.z * T_INV) * inv, 1.0f);
        sp.w = fminf(__expf(s.w * T_INV) * inv, 1.0f);
        sp4s[t] = sp;
    }
    __syncthreads();

    const int p  = tid & 63;
    const int cb = tid >> 6;                 // 0..3 ; channel = cb + 4*j
    const float4 sp = sp4s[p];

    const float4* xp = reinterpret_cast<const float4*>(x)
                     + (size_t)n * C_CH * HW4 + p0 + p;
    float4* op = reinterpret_cast<float4*>(out)
               + (size_t)n * C_CH * HW4 + p0 + p;

    #pragma unroll
    for (int i = 0; i < 2; i++) {
        float4 v[8];
        #pragma unroll
        for (int j = 0; j < 8; j++) {
            const int c = cb + (i * 8 + j) * 4;
            v[j] = __ldcs(&xp[(size_t)c * HW4]);    // last use, evict-first
        }
        #pragma unroll
        for (int j = 0; j < 8; j++) {
            const int c = cb + (i * 8 + j) * 4;
            const float a0 = a0s[c], a1 = a1s[c];
            const float b0 = b0s[c], b1 = b1s[c];
            float4 o;
            o.x = sp.x * fmaxf(fmaf(v[j].x, a0, b0), fmaf(v[j].x, a1, b1));
            o.y = sp.y * fmaxf(fmaf(v[j].y, a0, b0), fmaf(v[j].y, a1, b1));
            o.z = sp.z * fmaxf(fmaf(v[j].z, a0, b0), fmaf(v[j].z, a1, b1));
            o.w = sp.w * fmaxf(fmaf(v[j].w, a0, b0), fmaf(v[j].w, a1, b1));
            __stwt(&op[(size_t)c * HW4], o);        // write-through, no L2 alloc
        }
    }
}

extern "C" void kernel_launch(void* const* d_in, const int* in_sizes, int n_in,
                              void* d_out, int out_size)
{
    const float* x      = (const float*)d_in[0];
    const float* conv_w = (const float*)d_in[1];
    const float* conv_b = (const float*)d_in[2];
    const float* w1     = (const float*)d_in[3];
    const float* b1     = (const float*)d_in[4];
    const float* w2     = (const float*)d_in[5];
    const float* b2     = (const float*)d_in[6];
    float* out = (float*)d_out;

    k1_reduce<<<dim3(NB, N_S), 256>>>(x, conv_w, conv_b, w1, b1, w2, b2);
    k4_out<<<dim3(49, N_S), 256>>>(x, out);
}

// round 7
// speedup vs baseline: 1.1013x; 1.1013x over previous
#include <cuda_runtime.h>
#include <cuda_bf16.h>

#define N_S    32
#define C_CH   64
#define HWsz   12544
#define HW4    3136            // HW / 4 (float4)
#define NBK    25              // k1 blocks per sample (25*128 >= 3136)
#define HIDDEN 8
#define T_INV  (1.0f/10.0f)
#define GAMMA  (12544.0f/3.0f)

// Scratch (device globals — allocation is forbidden)
__device__ float4 g_s4[N_S * HW4];           // raw s (+bias)
__device__ float  g_cpart[N_S * NBK * C_CH]; // per-block channel partials
__device__ float  g_epart[N_S * NBK];        // per-block exp partials
__device__ float  g_coefA[N_S * 128];        // [n][k*64+c]
__device__ float  g_coefB[N_S * 128];
__device__ float  g_inv[N_S];                // GAMMA / sumexp

// ============ K1: read x once -> s, channel partials, exp partials ===========
// grid (25, 32), block 256. Warp w owns channels [8w,8w+8) over 128 pos4.
__global__ void __launch_bounds__(256) k1_reduce(
    const float* __restrict__ x,
    const float* __restrict__ conv_w, const float* __restrict__ conv_b)
{
    const int n    = blockIdx.y;
    const int bx   = blockIdx.x;
    const int base = bx * 128;
    const int tid  = threadIdx.x;
    const int warp = tid >> 5, lane = tid & 31;
    const int c0   = warp * 8;

    __shared__ float4 ssh[8][128];   // per-warp partial s (16 KB)
    __shared__ float  wsh[C_CH];
    __shared__ float  epart8[8];

    if (tid < C_CH) wsh[tid] = conv_w[tid];
    __syncthreads();

    float pool[8];
    #pragma unroll
    for (int i = 0; i < 8; i++) pool[i] = 0.f;

    const float4* xb = reinterpret_cast<const float4*>(x)
                     + ((size_t)n * C_CH + c0) * HW4 + base + lane;

    #pragma unroll
    for (int it = 0; it < 4; it++) {
        const int p  = it * 32 + lane;
        const bool ok = (base + p) < HW4;
        float4 s4 = make_float4(0.f, 0.f, 0.f, 0.f);
        #pragma unroll
        for (int c8 = 0; c8 < 8; c8++) {
            float4 v = ok ? xb[(size_t)c8 * HW4 + it * 32]
                          : make_float4(0.f, 0.f, 0.f, 0.f);
            float w = wsh[c0 + c8];
            pool[c8] += (v.x + v.y) + (v.z + v.w);
            s4.x = fmaf(v.x, w, s4.x); s4.y = fmaf(v.y, w, s4.y);
            s4.z = fmaf(v.z, w, s4.z); s4.w = fmaf(v.w, w, s4.w);
        }
        ssh[warp][p] = s4;
    }

    #pragma unroll
    for (int c8 = 0; c8 < 8; c8++) {
        float p = pool[c8];
        p += __shfl_down_sync(0xffffffff, p, 16);
        p += __shfl_down_sync(0xffffffff, p, 8);
        p += __shfl_down_sync(0xffffffff, p, 4);
        p += __shfl_down_sync(0xffffffff, p, 2);
        p += __shfl_down_sync(0xffffffff, p, 1);
        pool[c8] = p;
    }
    if (lane == 0) {
        float* dst = &g_cpart[((size_t)n * NBK + bx) * C_CH + c0];
        #pragma unroll
        for (int c8 = 0; c8 < 8; c8++) dst[c8] = pool[c8];
    }
    __syncthreads();

    // finalize s per position (threads 0..127), write raw s, exp partial
    float e = 0.f;
    if (tid < 128) {
        const int pos = base + tid;
        if (pos < HW4) {
            float4 s = ssh[0][tid];
            #pragma unroll
            for (int w = 1; w < 8; w++) {
                float4 t = ssh[w][tid];
                s.x += t.x; s.y += t.y; s.z += t.z; s.w += t.w;
            }
            const float bb = __ldg(conv_b);
            s.x += bb; s.y += bb; s.z += bb; s.w += bb;
            g_s4[n * HW4 + pos] = s;
            e = __expf(s.x * T_INV) + __expf(s.y * T_INV)
              + __expf(s.z * T_INV) + __expf(s.w * T_INV);
        }
    }
    e += __shfl_down_sync(0xffffffff, e, 16);
    e += __shfl_down_sync(0xffffffff, e, 8);
    e += __shfl_down_sync(0xffffffff, e, 4);
    e += __shfl_down_sync(0xffffffff, e, 2);
    e += __shfl_down_sync(0xffffffff, e, 1);
    if (lane == 0) epart8[warp] = e;
    __syncthreads();
    if (tid == 0)
        g_epart[n * NBK + bx] = epart8[0] + epart8[1] + epart8[2] + epart8[3];
}

// ============ K2: tiny — reduce partials, FC chain, coefs + inv ==============
// grid 32, block 256 (one block per sample)
__global__ void __launch_bounds__(256) k2_coef(
    const float* __restrict__ w1, const float* __restrict__ b1,
    const float* __restrict__ w2, const float* __restrict__ b2)
{
    const int n = blockIdx.x, tid = threadIdx.x;
    const int warp = tid >> 5, lane = tid & 31;

    __shared__ float red[4][C_CH];
    __shared__ float ps[C_CH];
    __shared__ float hs[HIDDEN];

    {
        const int c = tid & 63, q = tid >> 6;
        float a = 0.f;
        for (int j = q; j < NBK; j += 4)
            a += g_cpart[((size_t)n * NBK + j) * C_CH + c];
        red[q][c] = a;
    }
    if (warp == 0) {
        float se = 0.f;
        for (int j = lane; j < NBK; j += 32) se += g_epart[n * NBK + j];
        se += __shfl_down_sync(0xffffffff, se, 16);
        se += __shfl_down_sync(0xffffffff, se, 8);
        se += __shfl_down_sync(0xffffffff, se, 4);
        se += __shfl_down_sync(0xffffffff, se, 2);
        se += __shfl_down_sync(0xffffffff, se, 1);
        if (lane == 0) g_inv[n] = GAMMA / se;
    }
    __syncthreads();
    if (tid < C_CH)
        ps[tid] = (red[0][tid] + red[1][tid] + red[2][tid] + red[3][tid])
                * (1.0f / (float)HWsz);
    __syncthreads();
    if (tid < HIDDEN) {
        float a = __ldg(&b1[tid]);
        #pragma unroll
        for (int c = 0; c < C_CH; c++)
            a = fmaf(ps[c], __ldg(&w1[c * HIDDEN + tid]), a);
        hs[tid] = fmaxf(a, 0.0f);
    }
    __syncthreads();
    {
        float o = __ldg(&b2[tid]);
        #pragma unroll
        for (int j = 0; j < HIDDEN; j++)
            o = fmaf(hs[j], __ldg(&w2[j * 256 + tid]), o);
        float val = 2.0f / (1.0f + __expf(-o)) - 1.0f;   // 2*sigmoid-1
        const int sel = tid & 1;
        const int c   = (tid >> 1) & 63;
        const int k   = tid >> 7;
        const float init = (k == 0) ? 1.0f : 0.0f;
        if (sel == 0) g_coefA[n * 128 + k * 64 + c] = init + val;
        else          g_coefB[n * 128 + k * 64 + c] = init + 0.5f * val;
    }
}

// ================= K4: spatial + output pass (x re-read from L2) =============
// grid (49, 32), block 256: sample n, 64 pos4, all 64 channels.
// 8-deep __ldcs batches (MLP) + __stwt stores (no L2 allocate).
__global__ void __launch_bounds__(256, 5) k4_out(
    const float* __restrict__ x, float* __restrict__ out)
{
    const int n   = blockIdx.y;
    const int p0  = blockIdx.x * 64;
    const int tid = threadIdx.x;

    __shared__ float a0s[C_CH], a1s[C_CH], b0s[C_CH], b1s[C_CH];
    __shared__ float4 sp4s[64];

    if (tid < 64) {
        a0s[tid] = g_coefA[n * 128 + tid];
        a1s[tid] = g_coefA[n * 128 + 64 + tid];
        b0s[tid] = g_coefB[n * 128 + tid];
        b1s[tid] = g_coefB[n * 128 + 64 + tid];
    } else if (tid < 128) {
        const int t = tid - 64;
        const float inv = g_inv[n];
        float4 s = g_s4[n * HW4 + p0 + t];
        float4 sp;
        sp.x = fminf(__expf(s.x * T_INV) * inv, 1.0f);
        sp.y = fminf(__expf(s.y * T_INV) * inv, 1.0f);
        sp.z = fminf(__expf(s.z * T_INV) * inv, 1.0f);
        sp.w = fminf(__expf(s.w * T_INV) * inv, 1.0f);
        sp4s[t] = sp;
    }
    __syncthreads();

    const int p  = tid & 63;
    const int cb = tid >> 6;                 // 0..3 ; channel = cb + 4*j
    const float4 sp = sp4s[p];

    const float4* xp = reinterpret_cast<const float4*>(x)
                     + (size_t)n * C_CH * HW4 + p0 + p;
    float4* op = reinterpret_cast<float4*>(out)
               + (size_t)n * C_CH * HW4 + p0 + p;

    #pragma unroll
    for (int i = 0; i < 2; i++) {
        float4 v[8];
        #pragma unroll
        for (int j = 0; j < 8; j++) {
            const int c = cb + (i * 8 + j) * 4;
            v[j] = __ldcs(&xp[(size_t)c * HW4]);    // last use, evict-first
        }
        #pragma unroll
        for (int j = 0; j < 8; j++) {
            const int c = cb + (i * 8 + j) * 4;
            const float a0 = a0s[c], a1 = a1s[c];
            const float b0 = b0s[c], b1 = b1s[c];
            float4 o;
            o.x = sp.x * fmaxf(fmaf(v[j].x, a0, b0), fmaf(v[j].x, a1, b1));
            o.y = sp.y * fmaxf(fmaf(v[j].y, a0, b0), fmaf(v[j].y, a1, b1));
            o.z = sp.z * fmaxf(fmaf(v[j].z, a0, b0), fmaf(v[j].z, a1, b1));
            o.w = sp.w * fmaxf(fmaf(v[j].w, a0, b0), fmaf(v[j].w, a1, b1));
            __stwt(&op[(size_t)c * HW4], o);        // write-through, no L2 alloc
        }
    }
}

extern "C" void kernel_launch(void* const* d_in, const int* in_sizes, int n_in,
                              void* d_out, int out_size)
{
    const float* x      = (const float*)d_in[0];
    const float* conv_w = (const float*)d_in[1];
    const float* conv_b = (const float*)d_in[2];
    const float* w1     = (const float*)d_in[3];
    const float* b1     = (const float*)d_in[4];
    const float* w2     = (const float*)d_in[5];
    const float* b2     = (const float*)d_in[6];
    float* out = (float*)d_out;

    k1_reduce<<<dim3(NBK, N_S), 256>>>(x, conv_w, conv_b);
    k2_coef<<<N_S, 256>>>(w1, b1, w2, b2);
    k4_out<<<dim3(49, N_S), 256>>>(x, out);
}